// round 7
// baseline (speedup 1.0000x reference)
#include <cuda_runtime.h>
#include <cuda_bf16.h>
#include <math.h>

// Problem constants
#define B_  2
#define T_  2048
#define D_  2048
#define NH  16
#define NKV 4
#define HD  128
#define M_  (B_ * T_)          // 4096 rows for all GEMMs
#define ROPE_THETA 1000000.0

// ---------------------------------------------------------------------------
// Scratch (device globals; no allocation allowed)
// ---------------------------------------------------------------------------
__device__ float g_q[M_ * NH * HD];     // [B*T, 16*128]  32 MB
__device__ float g_k[M_ * NKV * HD];    // [B*T, 4*128]    8 MB
__device__ float g_v[M_ * NKV * HD];    //                 8 MB
__device__ float g_attn[M_ * NH * HD];  //                32 MB
__device__ float g_cos[T_ * HD];
__device__ float g_sin[T_ * HD];

// ---------------------------------------------------------------------------
// RoPE cache: cos/sin[t][d], d in [0,128), freq index = d % 64
// Computed in double: t*inv_freq reaches ~2047 rad; fp32 angles would inject
// ~2e-4 phase error. Doubles keep it exact to fp32 output precision.
// ---------------------------------------------------------------------------
__global__ void rope_cache_kernel() {
    int t = blockIdx.x;
    int d = threadIdx.x;            // 0..127
    int d2 = d & 63;
    double inv_freq = exp(-((double)(2 * d2) / (double)HD) * log(ROPE_THETA));
    double ang = (double)t * inv_freq;
    g_cos[t * HD + d] = (float)cos(ang);
    g_sin[t * HD + d] = (float)sin(ang);
}

// ---------------------------------------------------------------------------
// RoPE apply (in place): buf layout [B*T, nh, 128]
// first half:  a' = a*c - b*s ; second half: b' = b*c + a*s
// ---------------------------------------------------------------------------
__global__ void rope_apply_kernel(float* __restrict__ buf, int nh) {
    int idx = blockIdx.x * blockDim.x + threadIdx.x;      // over B*T*nh*64
    int total = M_ * nh * 64;
    if (idx >= total) return;
    int d2 = idx & 63;
    int h  = (idx >> 6) % nh;
    int bt = idx / (64 * nh);
    int t  = bt % T_;
    int base = (bt * nh + h) * HD;
    float a = buf[base + d2];
    float b = buf[base + d2 + 64];
    float c = g_cos[t * HD + d2];
    float s = g_sin[t * HD + d2];
    buf[base + d2]      = a * c - b * s;
    buf[base + d2 + 64] = b * c + a * s;
}

// ---------------------------------------------------------------------------
// SGEMM: C[M,N] = A[M,K] * B[K,N], all row-major, fp32.
// 128x128 tile, BK=16, 256 threads, 8x8 per thread.
// Double-buffered smem (ping-pong) with register-staged global prefetch:
// next tile's global loads issue BEFORE the FFMA block, so DRAM/L2 latency
// (577/234 cyc) hides under ~1024 FFMAs of compute per thread per tile.
// All dims are multiples of the tile sizes -> no bounds checks.
// ---------------------------------------------------------------------------
#define GBM 128
#define GBN 128
#define GBK 16

__global__ __launch_bounds__(256, 2)
void sgemm_kernel(const float* __restrict__ A, const float* __restrict__ Bm,
                  float* __restrict__ C, int M, int N, int K) {
    __shared__ float As[2][GBK][GBM];      // transposed A tiles (2 x 8 KB)
    __shared__ float Bs[2][GBK][GBN];      // (2 x 8 KB)

    int tid = threadIdx.x;
    int tx = tid & 15;                  // 0..15 (N direction)
    int ty = tid >> 4;                  // 0..15 (M direction)
    int bm = blockIdx.y * GBM;
    int bn = blockIdx.x * GBN;

    // A-load mapping: 128 rows x 16 k -> 512 float4; 2 per thread
    int a_row0 = tid >> 2;              // 0..63
    int a_k4   = (tid & 3) * 4;         // k offset of float4
    // B-load mapping: 16 k x 128 n -> 512 float4; 2 per thread
    int b_row0 = tid >> 5;              // 0..7
    int b_col  = (tid & 31) * 4;

    float acc[8][8];
    #pragma unroll
    for (int i = 0; i < 8; i++)
        #pragma unroll
        for (int j = 0; j < 8; j++) acc[i][j] = 0.0f;

    // ---- prologue: tile 0 straight into smem buffer 0 ----
    #pragma unroll
    for (int r = 0; r < 2; r++) {
        int row = a_row0 + r * 64;
        const float4 av = *reinterpret_cast<const float4*>(
            &A[(size_t)(bm + row) * K + a_k4]);
        As[0][a_k4 + 0][row] = av.x;
        As[0][a_k4 + 1][row] = av.y;
        As[0][a_k4 + 2][row] = av.z;
        As[0][a_k4 + 3][row] = av.w;
    }
    #pragma unroll
    for (int r = 0; r < 2; r++) {
        int row = b_row0 + r * 8;
        *reinterpret_cast<float4*>(&Bs[0][row][b_col]) =
            *reinterpret_cast<const float4*>(&Bm[(size_t)row * N + bn + b_col]);
    }
    __syncthreads();

    int ntiles = K / GBK;
    for (int it = 0; it < ntiles; ++it) {
        int cur = it & 1;
        int nxt = cur ^ 1;
        bool has_next = (it + 1 < ntiles);

        // prefetch next tile into registers (independent of compute below)
        float4 pa[2], pb[2];
        if (has_next) {
            int k0 = (it + 1) * GBK;
            #pragma unroll
            for (int r = 0; r < 2; r++) {
                pa[r] = *reinterpret_cast<const float4*>(
                    &A[(size_t)(bm + a_row0 + r * 64) * K + k0 + a_k4]);
                pb[r] = *reinterpret_cast<const float4*>(
                    &Bm[(size_t)(k0 + b_row0 + r * 8) * N + bn + b_col]);
            }
        }

        // compute on current smem tile
        #pragma unroll
        for (int kk = 0; kk < GBK; kk++) {
            float a[8], b[8];
            #pragma unroll
            for (int i = 0; i < 8; i++) a[i] = As[cur][kk][ty * 8 + i];
            #pragma unroll
            for (int j = 0; j < 8; j++) b[j] = Bs[cur][kk][tx * 8 + j];
            #pragma unroll
            for (int i = 0; i < 8; i++)
                #pragma unroll
                for (int j = 0; j < 8; j++)
                    acc[i][j] = fmaf(a[i], b[j], acc[i][j]);
        }

        // stage prefetched tile into the other smem buffer.
        // Safe without a pre-sync: everyone finished reading buffer `nxt`
        // at the __syncthreads() that ended the previous iteration.
        if (has_next) {
            #pragma unroll
            for (int r = 0; r < 2; r++) {
                int row = a_row0 + r * 64;
                As[nxt][a_k4 + 0][row] = pa[r].x;
                As[nxt][a_k4 + 1][row] = pa[r].y;
                As[nxt][a_k4 + 2][row] = pa[r].z;
                As[nxt][a_k4 + 3][row] = pa[r].w;
                *reinterpret_cast<float4*>(&Bs[nxt][b_row0 + r * 8][b_col]) = pb[r];
            }
        }
        __syncthreads();
    }

    #pragma unroll
    for (int i = 0; i < 8; i++) {
        int row = bm + ty * 8 + i;
        #pragma unroll
        for (int j = 0; j < 8; j += 4) {
            float4 v = make_float4(acc[i][j], acc[i][j+1], acc[i][j+2], acc[i][j+3]);
            *reinterpret_cast<float4*>(&C[(size_t)row * N + bn + tx * 8 + j]) = v;
        }
    }
}

// ---------------------------------------------------------------------------
// Causal GQA flash attention (fp32, streaming softmax).
// Grid: (T/8, B*NH). Block: 256 threads = 8 warps; warp w handles query row
// blockIdx.x*8 + w of head (blockIdx.y % NH), batch (blockIdx.y / NH).
// K/V tiles of 32 keys x 128 dims staged in smem.
// Full tiles (the common case) take an unrolled fast path.
// ---------------------------------------------------------------------------
#define FA_BN 32

#define FA_KEY_BODY(jj)                                                        \
    {                                                                          \
        float s = q0 * Ks[jj][lane] + q1 * Ks[jj][lane + 32]                   \
                + q2 * Ks[jj][lane + 64] + q3 * Ks[jj][lane + 96];             \
        s += __shfl_xor_sync(0xFFFFFFFF, s, 16);                               \
        s += __shfl_xor_sync(0xFFFFFFFF, s, 8);                                \
        s += __shfl_xor_sync(0xFFFFFFFF, s, 4);                                \
        s += __shfl_xor_sync(0xFFFFFFFF, s, 2);                                \
        s += __shfl_xor_sync(0xFFFFFFFF, s, 1);                                \
        s *= scale;                                                            \
        float m_new = fmaxf(m, s);                                             \
        float corr = __expf(m - m_new);  /* 0 when m == -inf */                \
        float p = __expf(s - m_new);                                           \
        l = l * corr + p;                                                      \
        o0 = o0 * corr + p * Vs[jj][lane];                                     \
        o1 = o1 * corr + p * Vs[jj][lane + 32];                                \
        o2 = o2 * corr + p * Vs[jj][lane + 64];                                \
        o3 = o3 * corr + p * Vs[jj][lane + 96];                                \
        m = m_new;                                                             \
    }

__global__ __launch_bounds__(256, 2)
void flash_attn_kernel() {
    __shared__ float Ks[FA_BN][HD];     // 16 KB
    __shared__ float Vs[FA_BN][HD];     // 16 KB

    int tid  = threadIdx.x;
    int warp = tid >> 5;
    int lane = tid & 31;
    int bh = blockIdx.y;
    int b  = bh / NH;
    int h  = bh % NH;
    int kvh = h >> 2;                   // GQA: h // (NH/NKV)
    int r  = blockIdx.x * 8 + warp;     // query row
    int row_max = blockIdx.x * 8 + 7;   // max row in this block

    const float scale = 0.08838834764831845f;   // 1/sqrt(128)

    // load q row: lane owns dims lane, lane+32, lane+64, lane+96
    float q0, q1, q2, q3;
    {
        size_t qb = ((size_t)(b * T_ + r) * NH + h) * HD;
        q0 = g_q[qb + lane];
        q1 = g_q[qb + lane + 32];
        q2 = g_q[qb + lane + 64];
        q3 = g_q[qb + lane + 96];
    }

    float m = -INFINITY, l = 0.0f;
    float o0 = 0.0f, o1 = 0.0f, o2 = 0.0f, o3 = 0.0f;

    for (int t0 = 0; t0 <= row_max; t0 += FA_BN) {
        // cooperative load of K/V tile: 1024 float4 each, 4 per thread
        #pragma unroll
        for (int i = 0; i < 4; i++) {
            int f4 = tid + 256 * i;         // 0..1023
            int jj = f4 >> 5;               // key within tile
            int c4 = (f4 & 31) * 4;         // dim offset
            size_t gb = ((size_t)(b * T_ + t0 + jj) * NKV + kvh) * HD + c4;
            *reinterpret_cast<float4*>(&Ks[jj][c4]) =
                *reinterpret_cast<const float4*>(&g_k[gb]);
            *reinterpret_cast<float4*>(&Vs[jj][c4]) =
                *reinterpret_cast<const float4*>(&g_v[gb]);
        }
        __syncthreads();

        int jmax = r - t0;                  // keys jj <= jmax are valid
        if (jmax >= FA_BN - 1) {
            // full tile: unrolled fast path (pipelines the shuffle chains)
            #pragma unroll 4
            for (int jj = 0; jj < FA_BN; jj++) FA_KEY_BODY(jj)
        } else {
            // diagonal tile tail
            for (int jj = 0; jj <= jmax; jj++) FA_KEY_BODY(jj)
        }
        __syncthreads();
    }

    float inv_l = 1.0f / l;
    size_t ob = ((size_t)(b * T_ + r) * NH + h) * HD;
    g_attn[ob + lane]       = o0 * inv_l;
    g_attn[ob + lane + 32]  = o1 * inv_l;
    g_attn[ob + lane + 64]  = o2 * inv_l;
    g_attn[ob + lane + 96]  = o3 * inv_l;
}

// ---------------------------------------------------------------------------
// Launch
// ---------------------------------------------------------------------------
extern "C" void kernel_launch(void* const* d_in, const int* in_sizes, int n_in,
                              void* d_out, int out_size) {
    const float* x  = (const float*)d_in[0];
    const float* wq = (const float*)d_in[1];
    const float* wk = (const float*)d_in[2];
    const float* wv = (const float*)d_in[3];
    const float* wo = (const float*)d_in[4];
    float* out = (float*)d_out;

    float *q, *k, *v, *attn;
    cudaGetSymbolAddress((void**)&q,    g_q);
    cudaGetSymbolAddress((void**)&k,    g_k);
    cudaGetSymbolAddress((void**)&v,    g_v);
    cudaGetSymbolAddress((void**)&attn, g_attn);

    // 1. RoPE cache
    rope_cache_kernel<<<T_, HD>>>();

    // 2. QKV projections
    {
        dim3 gq(D_ / GBN, M_ / GBM);                    // N=2048
        sgemm_kernel<<<gq, 256>>>(x, wq, q, M_, NH * HD, D_);
        dim3 gkv((NKV * HD) / GBN, M_ / GBM);           // N=512
        sgemm_kernel<<<gkv, 256>>>(x, wk, k, M_, NKV * HD, D_);
        sgemm_kernel<<<gkv, 256>>>(x, wv, v, M_, NKV * HD, D_);
    }

    // 3. RoPE on q and k
    {
        int nq = M_ * NH * 64;
        rope_apply_kernel<<<(nq + 255) / 256, 256>>>(q, NH);
        int nk = M_ * NKV * 64;
        rope_apply_kernel<<<(nk + 255) / 256, 256>>>(k, NKV);
    }

    // 4. Causal GQA attention
    {
        dim3 g(T_ / 8, B_ * NH);
        flash_attn_kernel<<<g, 256>>>();
    }

    // 5. Output projection -> d_out
    {
        dim3 go(D_ / GBN, M_ / GBM);
        sgemm_kernel<<<go, 256>>>(attn, wo, out, M_, D_, D_);
    }
}

// round 9
// speedup vs baseline: 1.4748x; 1.4748x over previous
#include <cuda_runtime.h>
#include <cuda_bf16.h>
#include <math.h>
#include <stdint.h>

// Problem constants
#define B_  2
#define T_  2048
#define D_  2048
#define NH  16
#define NKV 4
#define HD  128
#define M_  (B_ * T_)          // 4096
#define KVD (NKV * HD)         // 512
#define ROPE_THETA 1000000.0

// ---------------------------------------------------------------------------
// Scratch (device globals; no allocation allowed)
// ---------------------------------------------------------------------------
__device__ float g_q[M_ * NH * HD];     // 32 MB
__device__ float g_k[M_ * KVD];         //  8 MB
__device__ float g_v[M_ * KVD];         //  8 MB
__device__ float g_attn[M_ * NH * HD];  // 32 MB
__device__ float g_cos[T_ * HD];
__device__ float g_sin[T_ * HD];

// bf16 split-precision scratch (hi = bf16(x), lo = bf16(x - hi))
__device__ __nv_bfloat16 g_xh[M_ * D_],   g_xl[M_ * D_];    // x          [M][K]
__device__ __nv_bfloat16 g_ah[M_ * D_],   g_al[M_ * D_];    // attn       [M][K]
__device__ __nv_bfloat16 g_wqh[D_ * D_],  g_wql[D_ * D_];   // wq^T       [N][K]
__device__ __nv_bfloat16 g_woh[D_ * D_],  g_wol[D_ * D_];   // wo^T       [N][K]
__device__ __nv_bfloat16 g_wkh[KVD * D_], g_wkl[KVD * D_];  // wk^T
__device__ __nv_bfloat16 g_wvh[KVD * D_], g_wvl[KVD * D_];  // wv^T

// ---------------------------------------------------------------------------
// RoPE cache (double precision angles; t*inv_freq reaches ~2047 rad)
// ---------------------------------------------------------------------------
__global__ void rope_cache_kernel() {
    int t = blockIdx.x;
    int d = threadIdx.x;            // 0..127
    int d2 = d & 63;
    double inv_freq = exp(-((double)(2 * d2) / (double)HD) * log(ROPE_THETA));
    double ang = (double)t * inv_freq;
    g_cos[t * HD + d] = (float)cos(ang);
    g_sin[t * HD + d] = (float)sin(ang);
}

// ---------------------------------------------------------------------------
// RoPE apply (in place): buf layout [B*T, nh, 128]
// ---------------------------------------------------------------------------
__global__ void rope_apply_kernel(float* __restrict__ buf, int nh) {
    int idx = blockIdx.x * blockDim.x + threadIdx.x;
    int total = M_ * nh * 64;
    if (idx >= total) return;
    int d2 = idx & 63;
    int h  = (idx >> 6) % nh;
    int bt = idx / (64 * nh);
    int t  = bt % T_;
    int base = (bt * nh + h) * HD;
    float a = buf[base + d2];
    float b = buf[base + d2 + 64];
    float c = g_cos[t * HD + d2];
    float s = g_sin[t * HD + d2];
    buf[base + d2]      = a * c - b * s;
    buf[base + d2 + 64] = b * c + a * s;
}

// ---------------------------------------------------------------------------
// Split-bf16 conversions.
//   cvt_split : same layout (A operands, [M][K])
//   cvt_splitT: transpose to [N][K] (B operands) so GEMM reads K-contiguous
// ---------------------------------------------------------------------------
__global__ void cvt_split_kernel(const float* __restrict__ in,
                                 __nv_bfloat16* __restrict__ hi,
                                 __nv_bfloat16* __restrict__ lo, int n) {
    int i = blockIdx.x * blockDim.x + threadIdx.x;
    if (i >= n) return;
    float v = in[i];
    __nv_bfloat16 h = __float2bfloat16(v);
    hi[i] = h;
    lo[i] = __float2bfloat16(v - __bfloat162float(h));
}

__global__ void cvt_splitT_kernel(const float* __restrict__ in,
                                  __nv_bfloat16* __restrict__ hiT,
                                  __nv_bfloat16* __restrict__ loT, int K, int N) {
    int i = blockIdx.x * blockDim.x + threadIdx.x;
    if (i >= K * N) return;
    int k = i / N;
    int n = i - k * N;
    float v = in[i];
    __nv_bfloat16 h = __float2bfloat16(v);
    size_t o = (size_t)n * K + k;
    hiT[o] = h;
    loT[o] = __float2bfloat16(v - __bfloat162float(h));
}

// ---------------------------------------------------------------------------
// Split-bf16 tensor-core GEMM:
//   C[M][N] (fp32) = (Ah+Al)[M][K] * (Bh+Bl)^T[N][K]   (3-pass: hh + hl + lh)
// Block 128x128, 8 warps (2m x 4n), warp tile 64x32, mma.sync m16n8k16 bf16.
// Double-buffered smem via cp.async. Smem rows padded to 40 bf16 (80B) ->
// all fragment LDS.32 are bank-conflict-free; cp.async 16B-aligned.
// ---------------------------------------------------------------------------
#define TBM 128
#define TBN 128
#define TBK 32
#define SROW 40                        // bf16 elems per smem row (80 B)
#define TILE_BF (TBM * SROW)           // 5120 bf16 per matrix tile
#define GEMM_SMEM (2 * 4 * TILE_BF * 2)  // 81920 bytes

__device__ __forceinline__ void cp16(uint32_t dst, const void* src) {
    asm volatile("cp.async.cg.shared.global [%0], [%1], 16;\n"
                 :: "r"(dst), "l"(src));
}
#define CP_COMMIT() asm volatile("cp.async.commit_group;\n" ::: "memory")
#define CP_WAIT0()  asm volatile("cp.async.wait_group 0;\n" ::: "memory")

#define MMA_BF16(c, a, b)                                                    \
    asm volatile("mma.sync.aligned.m16n8k16.row.col.f32.bf16.bf16.f32 "      \
                 "{%0,%1,%2,%3},{%4,%5,%6,%7},{%8,%9},{%0,%1,%2,%3};\n"      \
                 : "+f"((c)[0]), "+f"((c)[1]), "+f"((c)[2]), "+f"((c)[3])    \
                 : "r"((a)[0]), "r"((a)[1]), "r"((a)[2]), "r"((a)[3]),       \
                   "r"((b)[0]), "r"((b)[1]))

__global__ void __launch_bounds__(256)
bgemm3_kernel(const __nv_bfloat16* __restrict__ Ah,
              const __nv_bfloat16* __restrict__ Al,
              const __nv_bfloat16* __restrict__ BhT,
              const __nv_bfloat16* __restrict__ BlT,
              float* __restrict__ C, int Ndim, int Kdim) {
    extern __shared__ __nv_bfloat16 sm[];   // [2 bufs][4 mats][TILE_BF]
    const int tid  = threadIdx.x;
    const int lane = tid & 31;
    const int warp = tid >> 5;
    const int wm = (warp >> 2) * 64;        // warp row offset in tile
    const int wn = (warp & 3) * 32;         // warp col offset in tile
    const int bm = blockIdx.y * TBM;
    const int bn = blockIdx.x * TBN;

    const uint32_t sbase = (uint32_t)__cvta_generic_to_shared(sm);

    float acc[4][4][4];
    #pragma unroll
    for (int mi = 0; mi < 4; mi++)
        #pragma unroll
        for (int ni = 0; ni < 4; ni++)
            #pragma unroll
            for (int t = 0; t < 4; t++) acc[mi][ni][t] = 0.0f;

    const __nv_bfloat16* gsrc[4] = {
        Ah  + (size_t)bm * Kdim,
        Al  + (size_t)bm * Kdim,
        BhT + (size_t)bn * Kdim,
        BlT + (size_t)bn * Kdim
    };

    // stage tile at k-offset kt into smem buffer bufi (cp.async, no regs held)
    auto stage = [&](int bufi, int kt) {
        uint32_t sb = sbase + (uint32_t)bufi * (4 * TILE_BF * 2);
        #pragma unroll
        for (int m = 0; m < 4; m++) {
            #pragma unroll
            for (int r = 0; r < 2; r++) {
                int idx = tid + 256 * r;            // 0..511 f16x8 groups
                int row = idx >> 2;                 // 0..127
                int g   = idx & 3;                  // 16B group within row
                uint32_t dst = sb + (uint32_t)m * (TILE_BF * 2)
                             + (uint32_t)row * (SROW * 2) + (uint32_t)g * 16;
                cp16(dst, gsrc[m] + (size_t)row * Kdim + kt + g * 8);
            }
        }
    };

    auto compute = [&](int bufi) {
        const __nv_bfloat16* sAh = sm + (size_t)bufi * (4 * TILE_BF);
        const __nv_bfloat16* sAl = sAh + TILE_BF;
        const __nv_bfloat16* sBh = sAl + TILE_BF;
        const __nv_bfloat16* sBl = sBh + TILE_BF;
        #pragma unroll
        for (int kk = 0; kk < TBK; kk += 16) {
            uint32_t ah[4][4], al[4][4], bh[4][2], bl[4][2];
            int colk = kk + (lane & 3) * 2;
            #pragma unroll
            for (int mi = 0; mi < 4; mi++) {
                int row = wm + mi * 16 + (lane >> 2);
                ah[mi][0] = *(const uint32_t*)&sAh[row * SROW + colk];
                ah[mi][1] = *(const uint32_t*)&sAh[(row + 8) * SROW + colk];
                ah[mi][2] = *(const uint32_t*)&sAh[row * SROW + colk + 8];
                ah[mi][3] = *(const uint32_t*)&sAh[(row + 8) * SROW + colk + 8];
                al[mi][0] = *(const uint32_t*)&sAl[row * SROW + colk];
                al[mi][1] = *(const uint32_t*)&sAl[(row + 8) * SROW + colk];
                al[mi][2] = *(const uint32_t*)&sAl[row * SROW + colk + 8];
                al[mi][3] = *(const uint32_t*)&sAl[(row + 8) * SROW + colk + 8];
            }
            #pragma unroll
            for (int ni = 0; ni < 4; ni++) {
                int nrow = wn + ni * 8 + (lane >> 2);
                bh[ni][0] = *(const uint32_t*)&sBh[nrow * SROW + colk];
                bh[ni][1] = *(const uint32_t*)&sBh[nrow * SROW + colk + 8];
                bl[ni][0] = *(const uint32_t*)&sBl[nrow * SROW + colk];
                bl[ni][1] = *(const uint32_t*)&sBl[nrow * SROW + colk + 8];
            }
            #pragma unroll
            for (int mi = 0; mi < 4; mi++)
                #pragma unroll
                for (int ni = 0; ni < 4; ni++) {
                    MMA_BF16(acc[mi][ni], ah[mi], bh[ni]);
                    MMA_BF16(acc[mi][ni], ah[mi], bl[ni]);
                    MMA_BF16(acc[mi][ni], al[mi], bh[ni]);
                }
        }
    };

    const int ntiles = Kdim / TBK;
    stage(0, 0);
    CP_COMMIT();
    CP_WAIT0();
    __syncthreads();

    for (int it = 0; it < ntiles; ++it) {
        int cur = it & 1;
        if (it + 1 < ntiles) {
            stage(cur ^ 1, (it + 1) * TBK);
            CP_COMMIT();
        }
        compute(cur);
        CP_WAIT0();
        __syncthreads();
    }

    // epilogue: fp32 C, float2 stores
    #pragma unroll
    for (int mi = 0; mi < 4; mi++) {
        int row = bm + wm + mi * 16 + (lane >> 2);
        #pragma unroll
        for (int ni = 0; ni < 4; ni++) {
            int col = bn + wn + ni * 8 + (lane & 3) * 2;
            *(float2*)&C[(size_t)row * Ndim + col] =
                make_float2(acc[mi][ni][0], acc[mi][ni][1]);
            *(float2*)&C[(size_t)(row + 8) * Ndim + col] =
                make_float2(acc[mi][ni][2], acc[mi][ni][3]);
        }
    }
}

// ---------------------------------------------------------------------------
// Causal GQA flash attention, lane-per-key mapping.
// Block 256 = 8 warps; warp w owns query row blockIdx.x*8+w.
// Per 32-key tile: lane j computes s_j fully (no per-key shuffles), softmax
// reduced once per tile (10 SHFL + 2 MUFU), P broadcast via smem, PV with
// vectorized V reads. All smem float4 traffic at the 4-phase LDS.128 floor.
// ---------------------------------------------------------------------------
#define FA_BN 32
#define KPAD 132     // HD + 4 -> row stride 528 B (16B-multiple, conflict-free)

__global__ __launch_bounds__(256, 2)
void flash_attn_kernel() {
    __shared__ float Ks[FA_BN][KPAD];   // 16.5 KB
    __shared__ float Vs[FA_BN][KPAD];   // 16.5 KB
    __shared__ float Qs[8][HD];         //  4 KB
    __shared__ float Ps[8][FA_BN];      //  1 KB

    const int tid  = threadIdx.x;
    const int warp = tid >> 5;
    const int lane = tid & 31;
    const int b   = blockIdx.y / NH;
    const int h   = blockIdx.y % NH;
    const int kvh = h >> 2;                    // GQA: h // (NH/NKV)
    const int r   = blockIdx.x * 8 + warp;     // this warp's query row
    const int rowmax = blockIdx.x * 8 + 7;

    const float scale = 0.08838834764831845f;  // 1/sqrt(128)

    // stage all 8 Q rows: thread t loads float4 group (t&31) of row (t>>5)
    {
        int qr = tid >> 5, g = tid & 31;
        *(float4*)&Qs[qr][4 * g] = *(const float4*)
            &g_q[((size_t)(b * T_ + blockIdx.x * 8 + qr) * NH + h) * HD + 4 * g];
    }
    __syncthreads();

    float m = -INFINITY, l = 0.0f;
    float4 o = make_float4(0.f, 0.f, 0.f, 0.f);

    for (int t0 = 0; t0 <= rowmax; t0 += FA_BN) {
        // K/V tile load: warp-coherent rows, 512B contiguous per warp-step
        #pragma unroll
        for (int i = 0; i < 4; i++) {
            int f4 = tid + 256 * i;
            int jj = f4 >> 5, g = f4 & 31;
            size_t gb = ((size_t)(b * T_ + t0 + jj) * NKV + kvh) * HD + 4 * g;
            *(float4*)&Ks[jj][4 * g] = *(const float4*)&g_k[gb];
            *(float4*)&Vs[jj][4 * g] = *(const float4*)&g_v[gb];
        }
        __syncthreads();

        // phase 1: lane j computes full dot for key t0+j (masked -> -inf)
        float s = -INFINITY;
        if (t0 + lane <= r) {
            float a = 0.0f;
            #pragma unroll
            for (int g = 0; g < 32; g++) {
                float4 k4 = *(const float4*)&Ks[lane][4 * g];
                float4 q4 = *(const float4*)&Qs[warp][4 * g];   // broadcast
                a += q4.x * k4.x + q4.y * k4.y + q4.z * k4.z + q4.w * k4.w;
            }
            s = a * scale;
        }

        // phase 2: tile-level softmax bookkeeping (one reduce per 32 keys)
        float tmax = s;
        #pragma unroll
        for (int off = 16; off; off >>= 1)
            tmax = fmaxf(tmax, __shfl_xor_sync(0xFFFFFFFF, tmax, off));
        float m_new = fmaxf(m, tmax);          // finite after first tile
        float p = __expf(s - m_new);           // s = -inf -> 0
        float psum = p;
        #pragma unroll
        for (int off = 16; off; off >>= 1)
            psum += __shfl_xor_sync(0xFFFFFFFF, psum, off);
        float corr = __expf(m - m_new);        // 0 on the first tile
        l = l * corr + psum;
        m = m_new;
        Ps[warp][lane] = p;
        __syncwarp();

        // phase 3: o[d] update; lane owns dims 4*lane .. 4*lane+3
        o.x *= corr; o.y *= corr; o.z *= corr; o.w *= corr;
        #pragma unroll
        for (int j = 0; j < FA_BN; j++) {
            float pj = Ps[warp][j];                         // broadcast
            float4 v4 = *(const float4*)&Vs[j][4 * lane];   // contiguous
            o.x += pj * v4.x; o.y += pj * v4.y;
            o.z += pj * v4.z; o.w += pj * v4.w;
        }
        __syncthreads();
    }

    float inv = 1.0f / l;
    o.x *= inv; o.y *= inv; o.z *= inv; o.w *= inv;
    *(float4*)&g_attn[((size_t)(b * T_ + r) * NH + h) * HD + 4 * lane] = o;
}

// ---------------------------------------------------------------------------
// Launch
// ---------------------------------------------------------------------------
extern "C" void kernel_launch(void* const* d_in, const int* in_sizes, int n_in,
                              void* d_out, int out_size) {
    const float* x  = (const float*)d_in[0];
    const float* wq = (const float*)d_in[1];
    const float* wk = (const float*)d_in[2];
    const float* wv = (const float*)d_in[3];
    const float* wo = (const float*)d_in[4];
    float* out = (float*)d_out;

    float *q, *k, *v, *attn;
    cudaGetSymbolAddress((void**)&q,    g_q);
    cudaGetSymbolAddress((void**)&k,    g_k);
    cudaGetSymbolAddress((void**)&v,    g_v);
    cudaGetSymbolAddress((void**)&attn, g_attn);

    __nv_bfloat16 *xh, *xl, *ah, *al, *wqh, *wql, *wkh, *wkl, *wvh, *wvl, *woh, *wol;
    cudaGetSymbolAddress((void**)&xh,  g_xh);  cudaGetSymbolAddress((void**)&xl,  g_xl);
    cudaGetSymbolAddress((void**)&ah,  g_ah);  cudaGetSymbolAddress((void**)&al,  g_al);
    cudaGetSymbolAddress((void**)&wqh, g_wqh); cudaGetSymbolAddress((void**)&wql, g_wql);
    cudaGetSymbolAddress((void**)&wkh, g_wkh); cudaGetSymbolAddress((void**)&wkl, g_wkl);
    cudaGetSymbolAddress((void**)&wvh, g_wvh); cudaGetSymbolAddress((void**)&wvl, g_wvl);
    cudaGetSymbolAddress((void**)&woh, g_woh); cudaGetSymbolAddress((void**)&wol, g_wol);

    cudaFuncSetAttribute(bgemm3_kernel,
                         cudaFuncAttributeMaxDynamicSharedMemorySize, GEMM_SMEM);

    // 1. RoPE cache
    rope_cache_kernel<<<T_, HD>>>();

    // 2. split-bf16 conversions (x and all weights; weights transposed)
    {
        int n = M_ * D_;
        cvt_split_kernel<<<(n + 255) / 256, 256>>>(x, xh, xl, n);
        int nw = D_ * D_;
        cvt_splitT_kernel<<<(nw + 255) / 256, 256>>>(wq, wqh, wql, D_, D_);
        cvt_splitT_kernel<<<(nw + 255) / 256, 256>>>(wo, woh, wol, D_, D_);
        int nk = D_ * KVD;
        cvt_splitT_kernel<<<(nk + 255) / 256, 256>>>(wk, wkh, wkl, D_, KVD);
        cvt_splitT_kernel<<<(nk + 255) / 256, 256>>>(wv, wvh, wvl, D_, KVD);
    }

    // 3. QKV projections (tensor cores, 3-pass split-bf16)
    {
        dim3 gq(D_ / TBN, M_ / TBM);                    // (16, 32)
        bgemm3_kernel<<<gq, 256, GEMM_SMEM>>>(xh, xl, wqh, wql, q, D_, D_);
        dim3 gkv(KVD / TBN, M_ / TBM);                  // (4, 32)
        bgemm3_kernel<<<gkv, 256, GEMM_SMEM>>>(xh, xl, wkh, wkl, k, KVD, D_);
        bgemm3_kernel<<<gkv, 256, GEMM_SMEM>>>(xh, xl, wvh, wvl, v, KVD, D_);
    }

    // 4. RoPE on q and k
    {
        int nq = M_ * NH * 64;
        rope_apply_kernel<<<(nq + 255) / 256, 256>>>(q, NH);
        int nk = M_ * NKV * 64;
        rope_apply_kernel<<<(nk + 255) / 256, 256>>>(k, NKV);
    }

    // 5. Causal GQA attention
    {
        dim3 g(T_ / 8, B_ * NH);
        flash_attn_kernel<<<g, 256>>>();
    }

    // 6. convert attention output, then output projection -> d_out
    {
        int n = M_ * D_;
        cvt_split_kernel<<<(n + 255) / 256, 256>>>(attn, ah, al, n);
        dim3 go(D_ / TBN, M_ / TBM);
        bgemm3_kernel<<<go, 256, GEMM_SMEM>>>(ah, al, woh, wol, out, D_, D_);
    }
}

// round 11
// speedup vs baseline: 1.6702x; 1.1325x over previous
#include <cuda_runtime.h>
#include <cuda_bf16.h>
#include <math.h>
#include <stdint.h>

// Problem constants
#define B_  2
#define T_  2048
#define D_  2048
#define NH  16
#define NKV 4
#define HD  128
#define M_  (B_ * T_)          // 4096
#define KVD (NKV * HD)         // 512
#define ROPE_THETA 1000000.0

// ---------------------------------------------------------------------------
// Scratch (device globals; no allocation allowed)
// ---------------------------------------------------------------------------
__device__ float g_q[M_ * NH * HD];     // 32 MB
__device__ float g_k[M_ * KVD];         //  8 MB
__device__ float g_v[M_ * KVD];         //  8 MB
__device__ float g_cos[T_ * HD];
__device__ float g_sin[T_ * HD];

// bf16 split-precision scratch (hi = bf16(x), lo = bf16(x - hi))
__device__ __nv_bfloat16 g_xh[M_ * D_],   g_xl[M_ * D_];    // x     [M][K]
__device__ __nv_bfloat16 g_ah[M_ * D_],   g_al[M_ * D_];    // attn  [M][K] (written by flash)
__device__ __nv_bfloat16 g_wqh[D_ * D_],  g_wql[D_ * D_];   // wq^T  [N][K]
__device__ __nv_bfloat16 g_woh[D_ * D_],  g_wol[D_ * D_];   // wo^T  [N][K]
__device__ __nv_bfloat16 g_wkh[KVD * D_], g_wkl[KVD * D_];  // wk^T
__device__ __nv_bfloat16 g_wvh[KVD * D_], g_wvl[KVD * D_];  // wv^T

// ---------------------------------------------------------------------------
// helpers
// ---------------------------------------------------------------------------
__device__ __forceinline__ void split2(float a, float b,
                                       unsigned& hi, unsigned& lo) {
    __nv_bfloat16 ha = __float2bfloat16(a), hb = __float2bfloat16(b);
    __nv_bfloat16 la = __float2bfloat16(a - __bfloat162float(ha));
    __nv_bfloat16 lb = __float2bfloat16(b - __bfloat162float(hb));
    hi = (unsigned)__bfloat16_as_ushort(ha) |
         ((unsigned)__bfloat16_as_ushort(hb) << 16);
    lo = (unsigned)__bfloat16_as_ushort(la) |
         ((unsigned)__bfloat16_as_ushort(lb) << 16);
}

__device__ __forceinline__ void cp16(uint32_t dst, const void* src) {
    asm volatile("cp.async.cg.shared.global [%0], [%1], 16;\n"
                 :: "r"(dst), "l"(src));
}
#define CP_COMMIT() asm volatile("cp.async.commit_group;\n" ::: "memory")
#define CP_WAIT0()  asm volatile("cp.async.wait_group 0;\n" ::: "memory")

// ---------------------------------------------------------------------------
// RoPE cache (double precision angles; t*inv_freq reaches ~2047 rad)
// ---------------------------------------------------------------------------
__global__ void rope_cache_kernel() {
    int t = blockIdx.x;
    int d = threadIdx.x;            // 0..127
    int d2 = d & 63;
    double inv_freq = exp(-((double)(2 * d2) / (double)HD) * log(ROPE_THETA));
    double ang = (double)t * inv_freq;
    g_cos[t * HD + d] = (float)cos(ang);
    g_sin[t * HD + d] = (float)sin(ang);
}

// ---------------------------------------------------------------------------
// RoPE apply (in place): buf layout [B*T, nh, 128]
// ---------------------------------------------------------------------------
__global__ void rope_apply_kernel(float* __restrict__ buf, int nh) {
    int idx = blockIdx.x * blockDim.x + threadIdx.x;
    int total = M_ * nh * 64;
    if (idx >= total) return;
    int d2 = idx & 63;
    int h  = (idx >> 6) % nh;
    int bt = idx / (64 * nh);
    int t  = bt % T_;
    int base = (bt * nh + h) * HD;
    float a = buf[base + d2];
    float b = buf[base + d2 + 64];
    float c = g_cos[t * HD + d2];
    float s = g_sin[t * HD + d2];
    buf[base + d2]      = a * c - b * s;
    buf[base + d2 + 64] = b * c + a * s;
}

// ---------------------------------------------------------------------------
// Split-bf16 conversions.
//   cvt_split : same layout, vectorized float4 in -> 8B hi + 8B lo out
//   cvt_splitT: smem-tiled transpose to [N][K]; coalesced loads AND stores
// ---------------------------------------------------------------------------
__global__ void cvt_split_kernel(const float* __restrict__ in,
                                 __nv_bfloat16* __restrict__ hi,
                                 __nv_bfloat16* __restrict__ lo, int n4) {
    int i = blockIdx.x * blockDim.x + threadIdx.x;
    if (i >= n4) return;
    float4 v = reinterpret_cast<const float4*>(in)[i];
    uint2 H, L;
    split2(v.x, v.y, H.x, L.x);
    split2(v.z, v.w, H.y, L.y);
    reinterpret_cast<uint2*>(hi)[i] = H;
    reinterpret_cast<uint2*>(lo)[i] = L;
}

__global__ void cvt_splitT_kernel(const float* __restrict__ in,
                                  __nv_bfloat16* __restrict__ hiT,
                                  __nv_bfloat16* __restrict__ loT,
                                  int K, int N) {
    __shared__ float tile[32][33];
    int n0 = blockIdx.x * 32, k0 = blockIdx.y * 32;
    int tx = threadIdx.x, ty = threadIdx.y;     // (32, 8)
    #pragma unroll
    for (int i = 0; i < 4; i++)
        tile[ty + 8 * i][tx] = in[(size_t)(k0 + ty + 8 * i) * N + n0 + tx];
    __syncthreads();
    #pragma unroll
    for (int i = 0; i < 4; i++) {
        float v = tile[tx][ty + 8 * i];         // = in[k0+tx][n0+ty+8i]
        __nv_bfloat16 hb = __float2bfloat16(v);
        size_t o = (size_t)(n0 + ty + 8 * i) * K + k0 + tx;
        hiT[o] = hb;
        loT[o] = __float2bfloat16(v - __bfloat162float(hb));
    }
}

// ---------------------------------------------------------------------------
// Split-bf16 tensor-core GEMM (unchanged from R8 win):
//   C[M][N] (fp32) = (Ah+Al)[M][K] * (Bh+Bl)^T[N][K]   (3-pass: hh + hl + lh)
// ---------------------------------------------------------------------------
#define TBM 128
#define TBN 128
#define TBK 32
#define SROW 40
#define TILE_BF (TBM * SROW)
#define GEMM_SMEM (2 * 4 * TILE_BF * 2)  // 81920 bytes

#define MMA_BF16(c, a, b)                                                    \
    asm volatile("mma.sync.aligned.m16n8k16.row.col.f32.bf16.bf16.f32 "      \
                 "{%0,%1,%2,%3},{%4,%5,%6,%7},{%8,%9},{%0,%1,%2,%3};\n"      \
                 : "+f"((c)[0]), "+f"((c)[1]), "+f"((c)[2]), "+f"((c)[3])    \
                 : "r"((a)[0]), "r"((a)[1]), "r"((a)[2]), "r"((a)[3]),       \
                   "r"((b)[0]), "r"((b)[1]))

__global__ void __launch_bounds__(256)
bgemm3_kernel(const __nv_bfloat16* __restrict__ Ah,
              const __nv_bfloat16* __restrict__ Al,
              const __nv_bfloat16* __restrict__ BhT,
              const __nv_bfloat16* __restrict__ BlT,
              float* __restrict__ C, int Ndim, int Kdim) {
    extern __shared__ __nv_bfloat16 sm[];   // [2 bufs][4 mats][TILE_BF]
    const int tid  = threadIdx.x;
    const int lane = tid & 31;
    const int warp = tid >> 5;
    const int wm = (warp >> 2) * 64;
    const int wn = (warp & 3) * 32;
    const int bm = blockIdx.y * TBM;
    const int bn = blockIdx.x * TBN;

    const uint32_t sbase = (uint32_t)__cvta_generic_to_shared(sm);

    float acc[4][4][4];
    #pragma unroll
    for (int mi = 0; mi < 4; mi++)
        #pragma unroll
        for (int ni = 0; ni < 4; ni++)
            #pragma unroll
            for (int t = 0; t < 4; t++) acc[mi][ni][t] = 0.0f;

    const __nv_bfloat16* gsrc[4] = {
        Ah  + (size_t)bm * Kdim,
        Al  + (size_t)bm * Kdim,
        BhT + (size_t)bn * Kdim,
        BlT + (size_t)bn * Kdim
    };

    auto stage = [&](int bufi, int kt) {
        uint32_t sb = sbase + (uint32_t)bufi * (4 * TILE_BF * 2);
        #pragma unroll
        for (int m = 0; m < 4; m++) {
            #pragma unroll
            for (int r = 0; r < 2; r++) {
                int idx = tid + 256 * r;
                int row = idx >> 2;
                int g   = idx & 3;
                uint32_t dst = sb + (uint32_t)m * (TILE_BF * 2)
                             + (uint32_t)row * (SROW * 2) + (uint32_t)g * 16;
                cp16(dst, gsrc[m] + (size_t)row * Kdim + kt + g * 8);
            }
        }
    };

    auto compute = [&](int bufi) {
        const __nv_bfloat16* sAh = sm + (size_t)bufi * (4 * TILE_BF);
        const __nv_bfloat16* sAl = sAh + TILE_BF;
        const __nv_bfloat16* sBh = sAl + TILE_BF;
        const __nv_bfloat16* sBl = sBh + TILE_BF;
        #pragma unroll
        for (int kk = 0; kk < TBK; kk += 16) {
            uint32_t ah[4][4], al[4][4], bh[4][2], bl[4][2];
            int colk = kk + (lane & 3) * 2;
            #pragma unroll
            for (int mi = 0; mi < 4; mi++) {
                int row = wm + mi * 16 + (lane >> 2);
                ah[mi][0] = *(const uint32_t*)&sAh[row * SROW + colk];
                ah[mi][1] = *(const uint32_t*)&sAh[(row + 8) * SROW + colk];
                ah[mi][2] = *(const uint32_t*)&sAh[row * SROW + colk + 8];
                ah[mi][3] = *(const uint32_t*)&sAh[(row + 8) * SROW + colk + 8];
                al[mi][0] = *(const uint32_t*)&sAl[row * SROW + colk];
                al[mi][1] = *(const uint32_t*)&sAl[(row + 8) * SROW + colk];
                al[mi][2] = *(const uint32_t*)&sAl[row * SROW + colk + 8];
                al[mi][3] = *(const uint32_t*)&sAl[(row + 8) * SROW + colk + 8];
            }
            #pragma unroll
            for (int ni = 0; ni < 4; ni++) {
                int nrow = wn + ni * 8 + (lane >> 2);
                bh[ni][0] = *(const uint32_t*)&sBh[nrow * SROW + colk];
                bh[ni][1] = *(const uint32_t*)&sBh[nrow * SROW + colk + 8];
                bl[ni][0] = *(const uint32_t*)&sBl[nrow * SROW + colk];
                bl[ni][1] = *(const uint32_t*)&sBl[nrow * SROW + colk + 8];
            }
            #pragma unroll
            for (int mi = 0; mi < 4; mi++)
                #pragma unroll
                for (int ni = 0; ni < 4; ni++) {
                    MMA_BF16(acc[mi][ni], ah[mi], bh[ni]);
                    MMA_BF16(acc[mi][ni], ah[mi], bl[ni]);
                    MMA_BF16(acc[mi][ni], al[mi], bh[ni]);
                }
        }
    };

    const int ntiles = Kdim / TBK;
    stage(0, 0);
    CP_COMMIT();
    CP_WAIT0();
    __syncthreads();

    for (int it = 0; it < ntiles; ++it) {
        int cur = it & 1;
        if (it + 1 < ntiles) {
            stage(cur ^ 1, (it + 1) * TBK);
            CP_COMMIT();
        }
        compute(cur);
        CP_WAIT0();
        __syncthreads();
    }

    #pragma unroll
    for (int mi = 0; mi < 4; mi++) {
        int row = bm + wm + mi * 16 + (lane >> 2);
        #pragma unroll
        for (int ni = 0; ni < 4; ni++) {
            int col = bn + wn + ni * 8 + (lane & 3) * 2;
            *(float2*)&C[(size_t)row * Ndim + col] =
                make_float2(acc[mi][ni][0], acc[mi][ni][1]);
            *(float2*)&C[(size_t)(row + 8) * Ndim + col] =
                make_float2(acc[mi][ni][2], acc[mi][ni][3]);
        }
    }
}

// ---------------------------------------------------------------------------
// Causal GQA flash attention, GQA-fused + double-buffered K/V.
// Block = 1024 threads = 32 warps = (4 q-heads sharing one kv-head) x (8 rows).
// K/V tiles (32 keys x 128) loaded ONCE per block via cp.async (ping-pong),
// serving all 4 heads -> 4x less L2 traffic than per-head blocks.
// Lane-per-key scoring; tile-level softmax reduce; P via smem broadcast.
// Output written directly as split-bf16 (g_ah/g_al) for the wo GEMM.
// ---------------------------------------------------------------------------
#define FA_BN 32
#define KPAD 132     // floats per K/V smem row (528 B; conflict-free float4)
#define KV_TILE (FA_BN * KPAD)              // floats per K or V tile
#define FLASH_SMEM ((2 * 2 * KV_TILE + 32 * HD + 32 * FA_BN) * 4)  // 88064 B

__global__ __launch_bounds__(1024, 1)
void flash_attn_kernel() {
    extern __shared__ float fsm[];
    float* Qs = fsm + 2 * 2 * KV_TILE;      // [32 warps][HD]
    float* Ps = Qs + 32 * HD;               // [32 warps][FA_BN]
    const uint32_t sbase = (uint32_t)__cvta_generic_to_shared(fsm);

    const int tid  = threadIdx.x;
    const int warp = tid >> 5;
    const int lane = tid & 31;
    const int b   = blockIdx.y / NKV;
    const int kvh = blockIdx.y % NKV;
    const int h   = kvh * 4 + (warp >> 3);     // this warp's q-head
    const int r   = blockIdx.x * 8 + (warp & 7);
    const int rowmax = blockIdx.x * 8 + 7;

    const float scale = 0.08838834764831845f;  // 1/sqrt(128)

    // stage Q: 1024 float4 = 32 (head,row) rows x 32 groups; 1 per thread
    {
        int qrow = tid >> 5;                   // matches warp indexing
        int hq = kvh * 4 + (qrow >> 3);
        int rq = blockIdx.x * 8 + (qrow & 7);
        int g  = tid & 31;
        *(float4*)&Qs[qrow * HD + 4 * g] = *(const float4*)
            &g_q[((size_t)(b * T_ + rq) * NH + hq) * HD + 4 * g];
    }

    auto stage_kv = [&](int bufi, int t0) {
        int jj = tid >> 5, g = tid & 31;       // 1 K float4 + 1 V float4/thread
        size_t gb = ((size_t)(b * T_ + t0 + jj) * NKV + kvh) * HD + 4 * g;
        uint32_t kdst = sbase +
            (uint32_t)(bufi * (2 * KV_TILE) + jj * KPAD + 4 * g) * 4u;
        cp16(kdst, &g_k[gb]);
        cp16(kdst + (uint32_t)KV_TILE * 4u, &g_v[gb]);
    };

    stage_kv(0, 0);
    CP_COMMIT();
    CP_WAIT0();
    __syncthreads();

    float m = -INFINITY, l = 0.0f;
    float4 o = make_float4(0.f, 0.f, 0.f, 0.f);

    const int ntiles = rowmax / FA_BN + 1;
    for (int it = 0; it < ntiles; ++it) {
        int t0  = it * FA_BN;
        int cur = it & 1;
        if (it + 1 < ntiles) {                 // prefetch next tile
            stage_kv(cur ^ 1, t0 + FA_BN);
            CP_COMMIT();
        }
        const float* Kst = fsm + cur * (2 * KV_TILE);
        const float* Vst = Kst + KV_TILE;

        // phase 1: lane j scores key t0+j (masked -> -inf)
        float s = -INFINITY;
        if (t0 + lane <= r) {
            float a = 0.0f;
            #pragma unroll
            for (int g = 0; g < 32; g++) {
                float4 k4 = *(const float4*)&Kst[lane * KPAD + 4 * g];
                float4 q4 = *(const float4*)&Qs[warp * HD + 4 * g];  // bcast
                a += q4.x * k4.x + q4.y * k4.y + q4.z * k4.z + q4.w * k4.w;
            }
            s = a * scale;
        }

        // phase 2: one softmax reduce per 32-key tile
        float tmax = s;
        #pragma unroll
        for (int off = 16; off; off >>= 1)
            tmax = fmaxf(tmax, __shfl_xor_sync(0xFFFFFFFF, tmax, off));
        float m_new = fmaxf(m, tmax);          // finite after first tile
        float p = __expf(s - m_new);           // -inf -> 0
        float psum = p;
        #pragma unroll
        for (int off = 16; off; off >>= 1)
            psum += __shfl_xor_sync(0xFFFFFFFF, psum, off);
        float corr = __expf(m - m_new);
        l = l * corr + psum;
        m = m_new;
        Ps[warp * FA_BN + lane] = p;
        __syncwarp();

        // phase 3: o update; lane owns dims 4*lane..4*lane+3
        o.x *= corr; o.y *= corr; o.z *= corr; o.w *= corr;
        #pragma unroll
        for (int j = 0; j < FA_BN; j++) {
            float pj = Ps[warp * FA_BN + j];               // bcast
            float4 v4 = *(const float4*)&Vst[j * KPAD + 4 * lane];
            o.x += pj * v4.x; o.y += pj * v4.y;
            o.z += pj * v4.z; o.w += pj * v4.w;
        }
        CP_WAIT0();
        __syncthreads();
    }

    // epilogue: split-bf16 write straight into the wo-GEMM A operand
    float inv = 1.0f / l;
    o.x *= inv; o.y *= inv; o.z *= inv; o.w *= inv;
    size_t base = ((size_t)(b * T_ + r) * NH + h) * HD + 4 * lane;
    uint2 H, L;
    split2(o.x, o.y, H.x, L.x);
    split2(o.z, o.w, H.y, L.y);
    *(uint2*)&g_ah[base] = H;
    *(uint2*)&g_al[base] = L;
}

// ---------------------------------------------------------------------------
// Launch
// ---------------------------------------------------------------------------
extern "C" void kernel_launch(void* const* d_in, const int* in_sizes, int n_in,
                              void* d_out, int out_size) {
    const float* x  = (const float*)d_in[0];
    const float* wq = (const float*)d_in[1];
    const float* wk = (const float*)d_in[2];
    const float* wv = (const float*)d_in[3];
    const float* wo = (const float*)d_in[4];
    float* out = (float*)d_out;

    float *q, *k, *v;
    cudaGetSymbolAddress((void**)&q, g_q);
    cudaGetSymbolAddress((void**)&k, g_k);
    cudaGetSymbolAddress((void**)&v, g_v);

    __nv_bfloat16 *xh, *xl, *ah, *al, *wqh, *wql, *wkh, *wkl, *wvh, *wvl, *woh, *wol;
    cudaGetSymbolAddress((void**)&xh,  g_xh);  cudaGetSymbolAddress((void**)&xl,  g_xl);
    cudaGetSymbolAddress((void**)&ah,  g_ah);  cudaGetSymbolAddress((void**)&al,  g_al);
    cudaGetSymbolAddress((void**)&wqh, g_wqh); cudaGetSymbolAddress((void**)&wql, g_wql);
    cudaGetSymbolAddress((void**)&wkh, g_wkh); cudaGetSymbolAddress((void**)&wkl, g_wkl);
    cudaGetSymbolAddress((void**)&wvh, g_wvh); cudaGetSymbolAddress((void**)&wvl, g_wvl);
    cudaGetSymbolAddress((void**)&woh, g_woh); cudaGetSymbolAddress((void**)&wol, g_wol);

    cudaFuncSetAttribute(bgemm3_kernel,
                         cudaFuncAttributeMaxDynamicSharedMemorySize, GEMM_SMEM);
    cudaFuncSetAttribute(flash_attn_kernel,
                         cudaFuncAttributeMaxDynamicSharedMemorySize, FLASH_SMEM);

    // 1. RoPE cache
    rope_cache_kernel<<<T_, HD>>>();

    // 2. split-bf16 conversions
    {
        int n4 = (M_ * D_) / 4;
        cvt_split_kernel<<<(n4 + 255) / 256, 256>>>(x, xh, xl, n4);
        dim3 blk(32, 8);
        cvt_splitT_kernel<<<dim3(D_ / 32, D_ / 32), blk>>>(wq, wqh, wql, D_, D_);
        cvt_splitT_kernel<<<dim3(D_ / 32, D_ / 32), blk>>>(wo, woh, wol, D_, D_);
        cvt_splitT_kernel<<<dim3(KVD / 32, D_ / 32), blk>>>(wk, wkh, wkl, D_, KVD);
        cvt_splitT_kernel<<<dim3(KVD / 32, D_ / 32), blk>>>(wv, wvh, wvl, D_, KVD);
    }

    // 3. QKV projections (tensor cores, 3-pass split-bf16)
    {
        dim3 gq(D_ / TBN, M_ / TBM);
        bgemm3_kernel<<<gq, 256, GEMM_SMEM>>>(xh, xl, wqh, wql, q, D_, D_);
        dim3 gkv(KVD / TBN, M_ / TBM);
        bgemm3_kernel<<<gkv, 256, GEMM_SMEM>>>(xh, xl, wkh, wkl, k, KVD, D_);
        bgemm3_kernel<<<gkv, 256, GEMM_SMEM>>>(xh, xl, wvh, wvl, v, KVD, D_);
    }

    // 4. RoPE on q and k
    {
        int nq = M_ * NH * 64;
        rope_apply_kernel<<<(nq + 255) / 256, 256>>>(q, NH);
        int nk = M_ * NKV * 64;
        rope_apply_kernel<<<(nk + 255) / 256, 256>>>(k, NKV);
    }

    // 5. Causal GQA attention (writes split-bf16 g_ah/g_al directly)
    {
        dim3 g(T_ / 8, B_ * NKV);
        flash_attn_kernel<<<g, 1024, FLASH_SMEM>>>();
    }

    // 6. Output projection -> d_out
    {
        dim3 go(D_ / TBN, M_ / TBM);
        bgemm3_kernel<<<go, 256, GEMM_SMEM>>>(ah, al, woh, wol, out, D_, D_);
    }
}

// round 13
// speedup vs baseline: 1.8443x; 1.1042x over previous
#include <cuda_runtime.h>
#include <cuda_bf16.h>
#include <cuda_fp16.h>
#include <math.h>
#include <stdint.h>

// Problem constants
#define B_  2
#define T_  2048
#define D_  2048
#define NH  16
#define NKV 4
#define HD  128
#define M_  (B_ * T_)          // 4096
#define KVD (NKV * HD)         // 512
#define ROPE_THETA 1000000.0

// ---------------------------------------------------------------------------
// Scratch (device globals; no allocation allowed)
// ---------------------------------------------------------------------------
__device__ float g_q[M_ * NH * HD];     // 32 MB
__device__ float g_k[M_ * KVD];         //  8 MB
__device__ float g_v[M_ * KVD];         //  8 MB
__device__ float g_cos[T_ * HD];
__device__ float g_sin[T_ * HD];

// fp16 GEMM operands.
// A-side: plain fp16 (activations). B-side: hi/lo fp16 split of weights,
// pre-transposed to [N][K] so the GEMM reads K-contiguous.
__device__ __half g_xh[M_ * D_];                      // x     [M][K]
__device__ __half g_ah[M_ * D_];                      // attn  [M][K] (flash writes)
__device__ __half g_wqh[D_ * D_],  g_wql[D_ * D_];    // wq^T
__device__ __half g_woh[D_ * D_],  g_wol[D_ * D_];    // wo^T
__device__ __half g_wkh[KVD * D_], g_wkl[KVD * D_];   // wk^T
__device__ __half g_wvh[KVD * D_], g_wvl[KVD * D_];   // wv^T

// ---------------------------------------------------------------------------
// helpers
// ---------------------------------------------------------------------------
__device__ __forceinline__ unsigned pack_h2(float a, float b) {
    __half ha = __float2half_rn(a), hb = __float2half_rn(b);
    return (unsigned)__half_as_ushort(ha) |
           ((unsigned)__half_as_ushort(hb) << 16);
}

__device__ __forceinline__ void cp16(uint32_t dst, const void* src) {
    asm volatile("cp.async.cg.shared.global [%0], [%1], 16;\n"
                 :: "r"(dst), "l"(src));
}
#define CP_COMMIT() asm volatile("cp.async.commit_group;\n" ::: "memory")
#define CP_WAIT0()  asm volatile("cp.async.wait_group 0;\n" ::: "memory")

// ---------------------------------------------------------------------------
// RoPE cache (double precision angles; t*inv_freq reaches ~2047 rad)
// ---------------------------------------------------------------------------
__global__ void rope_cache_kernel() {
    int t = blockIdx.x;
    int d = threadIdx.x;            // 0..127
    int d2 = d & 63;
    double inv_freq = exp(-((double)(2 * d2) / (double)HD) * log(ROPE_THETA));
    double ang = (double)t * inv_freq;
    g_cos[t * HD + d] = (float)cos(ang);
    g_sin[t * HD + d] = (float)sin(ang);
}

// ---------------------------------------------------------------------------
// RoPE apply (in place): buf layout [B*T, nh, 128]
// ---------------------------------------------------------------------------
__global__ void rope_apply_kernel(float* __restrict__ buf, int nh) {
    int idx = blockIdx.x * blockDim.x + threadIdx.x;
    int total = M_ * nh * 64;
    if (idx >= total) return;
    int d2 = idx & 63;
    int h  = (idx >> 6) % nh;
    int bt = idx / (64 * nh);
    int t  = bt % T_;
    int base = (bt * nh + h) * HD;
    float a = buf[base + d2];
    float b = buf[base + d2 + 64];
    float c = g_cos[t * HD + d2];
    float s = g_sin[t * HD + d2];
    buf[base + d2]      = a * c - b * s;
    buf[base + d2 + 64] = b * c + a * s;
}

// ---------------------------------------------------------------------------
// Conversions.
//   cvt_h      : fp32 -> fp16, same layout (A operands), float4 vectorized
//   cvt_splitT : fp32 -> fp16 hi/lo, transposed to [N][K] (B operands)
// ---------------------------------------------------------------------------
__global__ void cvt_h_kernel(const float* __restrict__ in,
                             __half* __restrict__ out, int n4) {
    int i = blockIdx.x * blockDim.x + threadIdx.x;
    if (i >= n4) return;
    float4 v = reinterpret_cast<const float4*>(in)[i];
    uint2 H;
    H.x = pack_h2(v.x, v.y);
    H.y = pack_h2(v.z, v.w);
    reinterpret_cast<uint2*>(out)[i] = H;
}

__global__ void cvt_splitT_kernel(const float* __restrict__ in,
                                  __half* __restrict__ hiT,
                                  __half* __restrict__ loT,
                                  int K, int N) {
    __shared__ float tile[32][33];
    int n0 = blockIdx.x * 32, k0 = blockIdx.y * 32;
    int tx = threadIdx.x, ty = threadIdx.y;     // (32, 8)
    #pragma unroll
    for (int i = 0; i < 4; i++)
        tile[ty + 8 * i][tx] = in[(size_t)(k0 + ty + 8 * i) * N + n0 + tx];
    __syncthreads();
    #pragma unroll
    for (int i = 0; i < 4; i++) {
        float v = tile[tx][ty + 8 * i];         // = in[k0+tx][n0+ty+8i]
        __half hb = __float2half_rn(v);
        size_t o = (size_t)(n0 + ty + 8 * i) * K + k0 + tx;
        hiT[o] = hb;
        loT[o] = __float2half_rn(v - __half2float(hb));
    }
}

// ---------------------------------------------------------------------------
// fp16 2-pass tensor-core GEMM:
//   C[M][N] fp32 = Ah[M][K] * (Bh + Bl)^T[N][K]
// (only omitted term is (A - Ah)*B, rel err ~1e-4)
// Block 128x128, 8 warps (2m x 4n), warp tile 64x32, mma.sync m16n8k16 f16.
// Double-buffered smem via cp.async; 3 matrices staged (Ah, Bh, Bl).
// Smem rows padded to 40 halves (80B): conflict-free LDS, 16B-aligned cp.
// 61.4 KB smem/CTA -> 2 CTAs/SM.
// ---------------------------------------------------------------------------
#define TBM 128
#define TBN 128
#define TBK 32
#define SROW 40
#define TILE_HF (TBM * SROW)             // 5120 halves per matrix tile
#define TILE_BYTES (TILE_HF * 2)         // 10240
#define GEMM_SMEM (2 * 3 * TILE_BYTES)   // 61440 bytes

#define MMA_F16(c, a, b)                                                     \
    asm volatile("mma.sync.aligned.m16n8k16.row.col.f32.f16.f16.f32 "        \
                 "{%0,%1,%2,%3},{%4,%5,%6,%7},{%8,%9},{%0,%1,%2,%3};\n"      \
                 : "+f"((c)[0]), "+f"((c)[1]), "+f"((c)[2]), "+f"((c)[3])    \
                 : "r"((a)[0]), "r"((a)[1]), "r"((a)[2]), "r"((a)[3]),       \
                   "r"((b)[0]), "r"((b)[1]))

__global__ void __launch_bounds__(256, 2)
fgemm2_kernel(const __half* __restrict__ Ah,
              const __half* __restrict__ BhT,
              const __half* __restrict__ BlT,
              float* __restrict__ C, int Ndim, int Kdim) {
    extern __shared__ __half sm[];   // [2 bufs][3 mats][TILE_HF]
    const int tid  = threadIdx.x;
    const int lane = tid & 31;
    const int warp = tid >> 5;
    const int wm = (warp >> 2) * 64;
    const int wn = (warp & 3) * 32;
    const int bm = blockIdx.y * TBM;
    const int bn = blockIdx.x * TBN;

    const uint32_t sbase = (uint32_t)__cvta_generic_to_shared(sm);

    float acc[4][4][4];
    #pragma unroll
    for (int mi = 0; mi < 4; mi++)
        #pragma unroll
        for (int ni = 0; ni < 4; ni++)
            #pragma unroll
            for (int t = 0; t < 4; t++) acc[mi][ni][t] = 0.0f;

    const __half* gsrc[3] = {
        Ah  + (size_t)bm * Kdim,
        BhT + (size_t)bn * Kdim,
        BlT + (size_t)bn * Kdim
    };

    // stage one K32 tile of 3 matrices: 3*512 16B chunks, 6 per thread
    auto stage = [&](int bufi, int kt) {
        uint32_t sb = sbase + (uint32_t)bufi * (3 * TILE_BYTES);
        #pragma unroll
        for (int i = 0; i < 6; i++) {
            int idx = tid + 256 * i;            // 0..1535
            int mat = idx >> 9;                 // 0..2
            int j   = idx & 511;
            int row = j >> 2;                   // 0..127
            int g   = j & 3;                    // 16B group
            uint32_t dst = sb + (uint32_t)mat * TILE_BYTES
                         + (uint32_t)row * (SROW * 2) + (uint32_t)g * 16;
            cp16(dst, gsrc[mat] + (size_t)row * Kdim + kt + g * 8);
        }
    };

    auto compute = [&](int bufi) {
        const __half* sA  = sm + (size_t)bufi * (3 * TILE_HF);
        const __half* sBh = sA + TILE_HF;
        const __half* sBl = sBh + TILE_HF;
        #pragma unroll
        for (int kk = 0; kk < TBK; kk += 16) {
            uint32_t a[4][4], bh[4][2], bl[4][2];
            int colk = kk + (lane & 3) * 2;
            #pragma unroll
            for (int mi = 0; mi < 4; mi++) {
                int row = wm + mi * 16 + (lane >> 2);
                a[mi][0] = *(const uint32_t*)&sA[row * SROW + colk];
                a[mi][1] = *(const uint32_t*)&sA[(row + 8) * SROW + colk];
                a[mi][2] = *(const uint32_t*)&sA[row * SROW + colk + 8];
                a[mi][3] = *(const uint32_t*)&sA[(row + 8) * SROW + colk + 8];
            }
            #pragma unroll
            for (int ni = 0; ni < 4; ni++) {
                int nrow = wn + ni * 8 + (lane >> 2);
                bh[ni][0] = *(const uint32_t*)&sBh[nrow * SROW + colk];
                bh[ni][1] = *(const uint32_t*)&sBh[nrow * SROW + colk + 8];
                bl[ni][0] = *(const uint32_t*)&sBl[nrow * SROW + colk];
                bl[ni][1] = *(const uint32_t*)&sBl[nrow * SROW + colk + 8];
            }
            #pragma unroll
            for (int mi = 0; mi < 4; mi++)
                #pragma unroll
                for (int ni = 0; ni < 4; ni++) {
                    MMA_F16(acc[mi][ni], a[mi], bh[ni]);
                    MMA_F16(acc[mi][ni], a[mi], bl[ni]);
                }
        }
    };

    const int ntiles = Kdim / TBK;
    stage(0, 0);
    CP_COMMIT();
    CP_WAIT0();
    __syncthreads();

    for (int it = 0; it < ntiles; ++it) {
        int cur = it & 1;
        if (it + 1 < ntiles) {
            stage(cur ^ 1, (it + 1) * TBK);
            CP_COMMIT();
        }
        compute(cur);
        CP_WAIT0();
        __syncthreads();
    }

    #pragma unroll
    for (int mi = 0; mi < 4; mi++) {
        int row = bm + wm + mi * 16 + (lane >> 2);
        #pragma unroll
        for (int ni = 0; ni < 4; ni++) {
            int col = bn + wn + ni * 8 + (lane & 3) * 2;
            *(float2*)&C[(size_t)row * Ndim + col] =
                make_float2(acc[mi][ni][0], acc[mi][ni][1]);
            *(float2*)&C[(size_t)(row + 8) * Ndim + col] =
                make_float2(acc[mi][ni][2], acc[mi][ni][3]);
        }
    }
}

// ---------------------------------------------------------------------------
// Causal GQA flash attention, GQA-fused + double-buffered K/V (R10 win).
// Block = 1024 threads = 32 warps = (4 q-heads) x (8 rows) per kv-head.
// Epilogue writes fp16 g_ah directly (A operand of the wo GEMM).
// ---------------------------------------------------------------------------
#define FA_BN 32
#define KPAD 132
#define KV_TILE (FA_BN * KPAD)
#define FLASH_SMEM ((2 * 2 * KV_TILE + 32 * HD + 32 * FA_BN) * 4)

__global__ __launch_bounds__(1024, 1)
void flash_attn_kernel() {
    extern __shared__ float fsm[];
    float* Qs = fsm + 2 * 2 * KV_TILE;
    float* Ps = Qs + 32 * HD;
    const uint32_t sbase = (uint32_t)__cvta_generic_to_shared(fsm);

    const int tid  = threadIdx.x;
    const int warp = tid >> 5;
    const int lane = tid & 31;
    const int b   = blockIdx.y / NKV;
    const int kvh = blockIdx.y % NKV;
    const int h   = kvh * 4 + (warp >> 3);
    const int r   = blockIdx.x * 8 + (warp & 7);
    const int rowmax = blockIdx.x * 8 + 7;

    const float scale = 0.08838834764831845f;

    {
        int qrow = tid >> 5;
        int hq = kvh * 4 + (qrow >> 3);
        int rq = blockIdx.x * 8 + (qrow & 7);
        int g  = tid & 31;
        *(float4*)&Qs[qrow * HD + 4 * g] = *(const float4*)
            &g_q[((size_t)(b * T_ + rq) * NH + hq) * HD + 4 * g];
    }

    auto stage_kv = [&](int bufi, int t0) {
        int jj = tid >> 5, g = tid & 31;
        size_t gb = ((size_t)(b * T_ + t0 + jj) * NKV + kvh) * HD + 4 * g;
        uint32_t kdst = sbase +
            (uint32_t)(bufi * (2 * KV_TILE) + jj * KPAD + 4 * g) * 4u;
        cp16(kdst, &g_k[gb]);
        cp16(kdst + (uint32_t)KV_TILE * 4u, &g_v[gb]);
    };

    stage_kv(0, 0);
    CP_COMMIT();
    CP_WAIT0();
    __syncthreads();

    float m = -INFINITY, l = 0.0f;
    float4 o = make_float4(0.f, 0.f, 0.f, 0.f);

    const int ntiles = rowmax / FA_BN + 1;
    for (int it = 0; it < ntiles; ++it) {
        int t0  = it * FA_BN;
        int cur = it & 1;
        if (it + 1 < ntiles) {
            stage_kv(cur ^ 1, t0 + FA_BN);
            CP_COMMIT();
        }
        const float* Kst = fsm + cur * (2 * KV_TILE);
        const float* Vst = Kst + KV_TILE;

        float s = -INFINITY;
        if (t0 + lane <= r) {
            float a = 0.0f;
            #pragma unroll
            for (int g = 0; g < 32; g++) {
                float4 k4 = *(const float4*)&Kst[lane * KPAD + 4 * g];
                float4 q4 = *(const float4*)&Qs[warp * HD + 4 * g];
                a += q4.x * k4.x + q4.y * k4.y + q4.z * k4.z + q4.w * k4.w;
            }
            s = a * scale;
        }

        float tmax = s;
        #pragma unroll
        for (int off = 16; off; off >>= 1)
            tmax = fmaxf(tmax, __shfl_xor_sync(0xFFFFFFFF, tmax, off));
        float m_new = fmaxf(m, tmax);
        float p = __expf(s - m_new);
        float psum = p;
        #pragma unroll
        for (int off = 16; off; off >>= 1)
            psum += __shfl_xor_sync(0xFFFFFFFF, psum, off);
        float corr = __expf(m - m_new);
        l = l * corr + psum;
        m = m_new;
        Ps[warp * FA_BN + lane] = p;
        __syncwarp();

        o.x *= corr; o.y *= corr; o.z *= corr; o.w *= corr;
        #pragma unroll
        for (int j = 0; j < FA_BN; j++) {
            float pj = Ps[warp * FA_BN + j];
            float4 v4 = *(const float4*)&Vst[j * KPAD + 4 * lane];
            o.x += pj * v4.x; o.y += pj * v4.y;
            o.z += pj * v4.z; o.w += pj * v4.w;
        }
        CP_WAIT0();
        __syncthreads();
    }

    // epilogue: fp16 write straight into the wo-GEMM A operand
    float inv = 1.0f / l;
    o.x *= inv; o.y *= inv; o.z *= inv; o.w *= inv;
    size_t base = ((size_t)(b * T_ + r) * NH + h) * HD + 4 * lane;
    uint2 H;
    H.x = pack_h2(o.x, o.y);
    H.y = pack_h2(o.z, o.w);
    *(uint2*)&g_ah[base] = H;
}

// ---------------------------------------------------------------------------
// Launch
// ---------------------------------------------------------------------------
extern "C" void kernel_launch(void* const* d_in, const int* in_sizes, int n_in,
                              void* d_out, int out_size) {
    const float* x  = (const float*)d_in[0];
    const float* wq = (const float*)d_in[1];
    const float* wk = (const float*)d_in[2];
    const float* wv = (const float*)d_in[3];
    const float* wo = (const float*)d_in[4];
    float* out = (float*)d_out;

    float *q, *k, *v;
    cudaGetSymbolAddress((void**)&q, g_q);
    cudaGetSymbolAddress((void**)&k, g_k);
    cudaGetSymbolAddress((void**)&v, g_v);

    __half *xh, *ah, *wqh, *wql, *wkh, *wkl, *wvh, *wvl, *woh, *wol;
    cudaGetSymbolAddress((void**)&xh,  g_xh);
    cudaGetSymbolAddress((void**)&ah,  g_ah);
    cudaGetSymbolAddress((void**)&wqh, g_wqh); cudaGetSymbolAddress((void**)&wql, g_wql);
    cudaGetSymbolAddress((void**)&wkh, g_wkh); cudaGetSymbolAddress((void**)&wkl, g_wkl);
    cudaGetSymbolAddress((void**)&wvh, g_wvh); cudaGetSymbolAddress((void**)&wvl, g_wvl);
    cudaGetSymbolAddress((void**)&woh, g_woh); cudaGetSymbolAddress((void**)&wol, g_wol);

    cudaFuncSetAttribute(fgemm2_kernel,
                         cudaFuncAttributeMaxDynamicSharedMemorySize, GEMM_SMEM);
    cudaFuncSetAttribute(flash_attn_kernel,
                         cudaFuncAttributeMaxDynamicSharedMemorySize, FLASH_SMEM);

    // 1. RoPE cache
    rope_cache_kernel<<<T_, HD>>>();

    // 2. conversions: x -> fp16; weights -> transposed fp16 hi/lo split
    {
        int n4 = (M_ * D_) / 4;
        cvt_h_kernel<<<(n4 + 255) / 256, 256>>>(x, xh, n4);
        dim3 blk(32, 8);
        cvt_splitT_kernel<<<dim3(D_ / 32, D_ / 32), blk>>>(wq, wqh, wql, D_, D_);
        cvt_splitT_kernel<<<dim3(D_ / 32, D_ / 32), blk>>>(wo, woh, wol, D_, D_);
        cvt_splitT_kernel<<<dim3(KVD / 32, D_ / 32), blk>>>(wk, wkh, wkl, D_, KVD);
        cvt_splitT_kernel<<<dim3(KVD / 32, D_ / 32), blk>>>(wv, wvh, wvl, D_, KVD);
    }

    // 3. QKV projections (fp16 2-pass tensor-core GEMM)
    {
        dim3 gq(D_ / TBN, M_ / TBM);
        fgemm2_kernel<<<gq, 256, GEMM_SMEM>>>(xh, wqh, wql, q, D_, D_);
        dim3 gkv(KVD / TBN, M_ / TBM);
        fgemm2_kernel<<<gkv, 256, GEMM_SMEM>>>(xh, wkh, wkl, k, KVD, D_);
        fgemm2_kernel<<<gkv, 256, GEMM_SMEM>>>(xh, wvh, wvl, v, KVD, D_);
    }

    // 4. RoPE on q and k
    {
        int nq = M_ * NH * 64;
        rope_apply_kernel<<<(nq + 255) / 256, 256>>>(q, NH);
        int nk = M_ * NKV * 64;
        rope_apply_kernel<<<(nk + 255) / 256, 256>>>(k, NKV);
    }

    // 5. Causal GQA attention (writes fp16 g_ah directly)
    {
        dim3 g(T_ / 8, B_ * NKV);
        flash_attn_kernel<<<g, 1024, FLASH_SMEM>>>();
    }

    // 6. Output projection -> d_out
    {
        dim3 go(D_ / TBN, M_ / TBM);
        fgemm2_kernel<<<go, 256, GEMM_SMEM>>>(ah, woh, wol, out, D_, D_);
    }
}

// round 14
// speedup vs baseline: 3.0494x; 1.6534x over previous
#include <cuda_runtime.h>
#include <cuda_bf16.h>
#include <cuda_fp16.h>
#include <math.h>
#include <stdint.h>

// Problem constants
#define B_  2
#define T_  2048
#define D_  2048
#define NH  16
#define NKV 4
#define HD  128
#define M_  (B_ * T_)          // 4096
#define KVD (NKV * HD)         // 512
#define ROPE_THETA 1000000.0

// ---------------------------------------------------------------------------
// Scratch (device globals; no allocation allowed)
// ---------------------------------------------------------------------------
__device__ float g_q[M_ * NH * HD];     // 32 MB
__device__ float g_k[M_ * KVD];         //  8 MB
__device__ float g_v[M_ * KVD];         //  8 MB
__device__ float g_cos[T_ * HD];
__device__ float g_sin[T_ * HD];

// fp16 GEMM operands.
// A-side: plain fp16 (activations). B-side: hi/lo fp16 split of weights,
// pre-transposed to [N][K] so the GEMM reads K-contiguous.
__device__ __half g_xh[M_ * D_];                      // x     [M][K]
__device__ __half g_ah[M_ * D_];                      // attn  [M][K] (flash writes)
__device__ __half g_wqh[D_ * D_],  g_wql[D_ * D_];    // wq^T
__device__ __half g_woh[D_ * D_],  g_wol[D_ * D_];    // wo^T
__device__ __half g_wkh[KVD * D_], g_wkl[KVD * D_];   // wk^T
__device__ __half g_wvh[KVD * D_], g_wvl[KVD * D_];   // wv^T

// ---------------------------------------------------------------------------
// helpers
// ---------------------------------------------------------------------------
__device__ __forceinline__ unsigned pack_h2(float a, float b) {
    __half ha = __float2half_rn(a), hb = __float2half_rn(b);
    return (unsigned)__half_as_ushort(ha) |
           ((unsigned)__half_as_ushort(hb) << 16);
}

__device__ __forceinline__ void cp16(uint32_t dst, const void* src) {
    asm volatile("cp.async.cg.shared.global [%0], [%1], 16;\n"
                 :: "r"(dst), "l"(src));
}
#define CP_COMMIT() asm volatile("cp.async.commit_group;\n" ::: "memory")
#define CP_WAIT0()  asm volatile("cp.async.wait_group 0;\n" ::: "memory")

// ---------------------------------------------------------------------------
// RoPE cache (double precision angles; t*inv_freq reaches ~2047 rad)
// ---------------------------------------------------------------------------
__global__ void rope_cache_kernel() {
    int t = blockIdx.x;
    int d = threadIdx.x;            // 0..127
    int d2 = d & 63;
    double inv_freq = exp(-((double)(2 * d2) / (double)HD) * log(ROPE_THETA));
    double ang = (double)t * inv_freq;
    g_cos[t * HD + d] = (float)cos(ang);
    g_sin[t * HD + d] = (float)sin(ang);
}

// ---------------------------------------------------------------------------
// RoPE apply (in place): buf layout [B*T, nh, 128]
// ---------------------------------------------------------------------------
__global__ void rope_apply_kernel(float* __restrict__ buf, int nh) {
    int idx = blockIdx.x * blockDim.x + threadIdx.x;
    int total = M_ * nh * 64;
    if (idx >= total) return;
    int d2 = idx & 63;
    int h  = (idx >> 6) % nh;
    int bt = idx / (64 * nh);
    int t  = bt % T_;
    int base = (bt * nh + h) * HD;
    float a = buf[base + d2];
    float b = buf[base + d2 + 64];
    float c = g_cos[t * HD + d2];
    float s = g_sin[t * HD + d2];
    buf[base + d2]      = a * c - b * s;
    buf[base + d2 + 64] = b * c + a * s;
}

// ---------------------------------------------------------------------------
// Conversions.
// ---------------------------------------------------------------------------
__global__ void cvt_h_kernel(const float* __restrict__ in,
                             __half* __restrict__ out, int n4) {
    int i = blockIdx.x * blockDim.x + threadIdx.x;
    if (i >= n4) return;
    float4 v = reinterpret_cast<const float4*>(in)[i];
    uint2 H;
    H.x = pack_h2(v.x, v.y);
    H.y = pack_h2(v.z, v.w);
    reinterpret_cast<uint2*>(out)[i] = H;
}

__global__ void cvt_splitT_kernel(const float* __restrict__ in,
                                  __half* __restrict__ hiT,
                                  __half* __restrict__ loT,
                                  int K, int N) {
    __shared__ float tile[32][33];
    int n0 = blockIdx.x * 32, k0 = blockIdx.y * 32;
    int tx = threadIdx.x, ty = threadIdx.y;     // (32, 8)
    #pragma unroll
    for (int i = 0; i < 4; i++)
        tile[ty + 8 * i][tx] = in[(size_t)(k0 + ty + 8 * i) * N + n0 + tx];
    __syncthreads();
    #pragma unroll
    for (int i = 0; i < 4; i++) {
        float v = tile[tx][ty + 8 * i];         // = in[k0+tx][n0+ty+8i]
        __half hb = __float2half_rn(v);
        size_t o = (size_t)(n0 + ty + 8 * i) * K + k0 + tx;
        hiT[o] = hb;
        loT[o] = __float2half_rn(v - __half2float(hb));
    }
}

// ---------------------------------------------------------------------------
// fp16 2-pass tensor-core GEMM (R12 win, unchanged):
//   C[M][N] fp32 = Ah[M][K] * (Bh + Bl)^T[N][K]
// ---------------------------------------------------------------------------
#define TBM 128
#define TBN 128
#define TBK 32
#define SROW 40
#define TILE_HF (TBM * SROW)
#define TILE_BYTES (TILE_HF * 2)
#define GEMM_SMEM (2 * 3 * TILE_BYTES)   // 61440 bytes

#define MMA_F16(c, a, b)                                                     \
    asm volatile("mma.sync.aligned.m16n8k16.row.col.f32.f16.f16.f32 "        \
                 "{%0,%1,%2,%3},{%4,%5,%6,%7},{%8,%9},{%0,%1,%2,%3};\n"      \
                 : "+f"((c)[0]), "+f"((c)[1]), "+f"((c)[2]), "+f"((c)[3])    \
                 : "r"((a)[0]), "r"((a)[1]), "r"((a)[2]), "r"((a)[3]),       \
                   "r"((b)[0]), "r"((b)[1]))

__global__ void __launch_bounds__(256, 2)
fgemm2_kernel(const __half* __restrict__ Ah,
              const __half* __restrict__ BhT,
              const __half* __restrict__ BlT,
              float* __restrict__ C, int Ndim, int Kdim) {
    extern __shared__ __half sm[];   // [2 bufs][3 mats][TILE_HF]
    const int tid  = threadIdx.x;
    const int lane = tid & 31;
    const int warp = tid >> 5;
    const int wm = (warp >> 2) * 64;
    const int wn = (warp & 3) * 32;
    const int bm = blockIdx.y * TBM;
    const int bn = blockIdx.x * TBN;

    const uint32_t sbase = (uint32_t)__cvta_generic_to_shared(sm);

    float acc[4][4][4];
    #pragma unroll
    for (int mi = 0; mi < 4; mi++)
        #pragma unroll
        for (int ni = 0; ni < 4; ni++)
            #pragma unroll
            for (int t = 0; t < 4; t++) acc[mi][ni][t] = 0.0f;

    const __half* gsrc[3] = {
        Ah  + (size_t)bm * Kdim,
        BhT + (size_t)bn * Kdim,
        BlT + (size_t)bn * Kdim
    };

    auto stage = [&](int bufi, int kt) {
        uint32_t sb = sbase + (uint32_t)bufi * (3 * TILE_BYTES);
        #pragma unroll
        for (int i = 0; i < 6; i++) {
            int idx = tid + 256 * i;
            int mat = idx >> 9;
            int j   = idx & 511;
            int row = j >> 2;
            int g   = j & 3;
            uint32_t dst = sb + (uint32_t)mat * TILE_BYTES
                         + (uint32_t)row * (SROW * 2) + (uint32_t)g * 16;
            cp16(dst, gsrc[mat] + (size_t)row * Kdim + kt + g * 8);
        }
    };

    auto compute = [&](int bufi) {
        const __half* sA  = sm + (size_t)bufi * (3 * TILE_HF);
        const __half* sBh = sA + TILE_HF;
        const __half* sBl = sBh + TILE_HF;
        #pragma unroll
        for (int kk = 0; kk < TBK; kk += 16) {
            uint32_t a[4][4], bh[4][2], bl[4][2];
            int colk = kk + (lane & 3) * 2;
            #pragma unroll
            for (int mi = 0; mi < 4; mi++) {
                int row = wm + mi * 16 + (lane >> 2);
                a[mi][0] = *(const uint32_t*)&sA[row * SROW + colk];
                a[mi][1] = *(const uint32_t*)&sA[(row + 8) * SROW + colk];
                a[mi][2] = *(const uint32_t*)&sA[row * SROW + colk + 8];
                a[mi][3] = *(const uint32_t*)&sA[(row + 8) * SROW + colk + 8];
            }
            #pragma unroll
            for (int ni = 0; ni < 4; ni++) {
                int nrow = wn + ni * 8 + (lane >> 2);
                bh[ni][0] = *(const uint32_t*)&sBh[nrow * SROW + colk];
                bh[ni][1] = *(const uint32_t*)&sBh[nrow * SROW + colk + 8];
                bl[ni][0] = *(const uint32_t*)&sBl[nrow * SROW + colk];
                bl[ni][1] = *(const uint32_t*)&sBl[nrow * SROW + colk + 8];
            }
            #pragma unroll
            for (int mi = 0; mi < 4; mi++)
                #pragma unroll
                for (int ni = 0; ni < 4; ni++) {
                    MMA_F16(acc[mi][ni], a[mi], bh[ni]);
                    MMA_F16(acc[mi][ni], a[mi], bl[ni]);
                }
        }
    };

    const int ntiles = Kdim / TBK;
    stage(0, 0);
    CP_COMMIT();
    CP_WAIT0();
    __syncthreads();

    for (int it = 0; it < ntiles; ++it) {
        int cur = it & 1;
        if (it + 1 < ntiles) {
            stage(cur ^ 1, (it + 1) * TBK);
            CP_COMMIT();
        }
        compute(cur);
        CP_WAIT0();
        __syncthreads();
    }

    #pragma unroll
    for (int mi = 0; mi < 4; mi++) {
        int row = bm + wm + mi * 16 + (lane >> 2);
        #pragma unroll
        for (int ni = 0; ni < 4; ni++) {
            int col = bn + wn + ni * 8 + (lane & 3) * 2;
            *(float2*)&C[(size_t)row * Ndim + col] =
                make_float2(acc[mi][ni][0], acc[mi][ni][1]);
            *(float2*)&C[(size_t)(row + 8) * Ndim + col] =
                make_float2(acc[mi][ni][2], acc[mi][ni][3]);
        }
    }
}

// ---------------------------------------------------------------------------
// Causal GQA flash attention, 8 query rows per warp (smem-traffic fix).
// Block = 512 threads = 16 warps = 4 q-heads x 4 warps; each warp owns 8
// contiguous query rows -> one K/V fragment LDS feeds 32 FFMA instead of 4.
// Grid (T/32, B*NKV): one K/V tile load serves 4 heads x 32 rows.
// K/V cp.async double-buffered; scores/softmax/PV all fp32 (numerics
// identical to R13). Output written as fp16 g_ah (wo-GEMM A operand).
// ---------------------------------------------------------------------------
#define FA_BN 32
#define KPAD 132
#define KV_TILE (FA_BN * KPAD)                         // 4224 floats
#define FA_QROWS 32                                    // query rows per block
#define FLASH_SMEM ((2 * 2 * KV_TILE + 128 * HD + 16 * FA_BN * 8) * 4) // 149504

__global__ __launch_bounds__(512, 1)
void flash_attn_kernel() {
    extern __shared__ float fsm[];
    float* Qs = fsm + 2 * 2 * KV_TILE;      // [128 (head,row) vecs][HD]
    float* Ps = Qs + 128 * HD;              // [16 warps][32 keys][8 rows]
    const uint32_t sbase = (uint32_t)__cvta_generic_to_shared(fsm);

    const int tid  = threadIdx.x;
    const int warp = tid >> 5;              // 0..15
    const int lane = tid & 31;
    const int b   = blockIdx.y / NKV;
    const int kvh = blockIdx.y % NKV;
    const int hg  = warp >> 2;              // 0..3: head within GQA group
    const int h   = kvh * 4 + hg;
    const int r0  = blockIdx.x * FA_QROWS + (warp & 3) * 8;  // first of 8 rows
    const int qbase = hg * 32 + (warp & 3) * 8;              // Qs row of rr=0

    const float scale = 0.08838834764831845f;  // 1/sqrt(128)

    // stage Q: 128 vecs x 32 float4 groups = 4096 float4; 8 per thread
    #pragma unroll
    for (int i = 0; i < 8; i++) {
        int idx = tid + 512 * i;
        int qi = idx >> 5, g = idx & 31;
        int hq = qi >> 5, lr = qi & 31;
        *(float4*)&Qs[qi * HD + 4 * g] = *(const float4*)
            &g_q[((size_t)(b * T_ + blockIdx.x * FA_QROWS + lr) * NH
                  + kvh * 4 + hq) * HD + 4 * g];
    }

    auto stage_kv = [&](int bufi, int t0) {
        #pragma unroll
        for (int i = 0; i < 2; i++) {
            int idx = tid + 512 * i;            // 0..1023
            int jj = idx >> 5, g = idx & 31;
            size_t gb = ((size_t)(b * T_ + t0 + jj) * NKV + kvh) * HD + 4 * g;
            uint32_t kdst = sbase +
                (uint32_t)(bufi * (2 * KV_TILE) + jj * KPAD + 4 * g) * 4u;
            cp16(kdst, &g_k[gb]);
            cp16(kdst + (uint32_t)KV_TILE * 4u, &g_v[gb]);
        }
    };

    stage_kv(0, 0);
    CP_COMMIT();
    CP_WAIT0();
    __syncthreads();

    float m[8], l[8];
    float4 o[8];
    #pragma unroll
    for (int rr = 0; rr < 8; rr++) {
        m[rr] = -INFINITY; l[rr] = 0.0f;
        o[rr] = make_float4(0.f, 0.f, 0.f, 0.f);
    }

    const int ntiles = blockIdx.x + 1;      // (bx*32+31)/32 + 1
    for (int it = 0; it < ntiles; ++it) {
        int t0  = it * FA_BN;
        int cur = it & 1;
        if (it + 1 < ntiles) {
            stage_kv(cur ^ 1, t0 + FA_BN);
            CP_COMMIT();
        }
        const float* Kst = fsm + cur * (2 * KV_TILE);
        const float* Vst = Kst + KV_TILE;

        // phase 1: lane j scores key t0+j against all 8 rows
        float a[8];
        #pragma unroll
        for (int rr = 0; rr < 8; rr++) a[rr] = 0.0f;
        #pragma unroll 4
        for (int g = 0; g < 32; g++) {
            float4 k4 = *(const float4*)&Kst[lane * KPAD + 4 * g];
            #pragma unroll
            for (int rr = 0; rr < 8; rr++) {
                float4 q4 = *(const float4*)&Qs[(qbase + rr) * HD + 4 * g];
                a[rr] += q4.x * k4.x + q4.y * k4.y + q4.z * k4.z + q4.w * k4.w;
            }
        }

        // phase 2: per-row streaming softmax bookkeeping
        float pv[8], corr[8];
        #pragma unroll
        for (int rr = 0; rr < 8; rr++) {
            float s = (t0 + lane <= r0 + rr) ? a[rr] * scale : -INFINITY;
            float tmax = s;
            #pragma unroll
            for (int off = 16; off; off >>= 1)
                tmax = fmaxf(tmax, __shfl_xor_sync(0xFFFFFFFF, tmax, off));
            float m_new = fmaxf(m[rr], tmax);
            float p = __expf(s - m_new);        // -inf -> 0
            float psum = p;
            #pragma unroll
            for (int off = 16; off; off >>= 1)
                psum += __shfl_xor_sync(0xFFFFFFFF, psum, off);
            corr[rr] = __expf(m[rr] - m_new);   // 0 on first live tile
            l[rr] = l[rr] * corr[rr] + psum;
            m[rr] = m_new;
            pv[rr] = p;
        }
        // store P: lane j writes its 8 rows' p at Ps[warp][j][0..7]
        *(float4*)&Ps[warp * 256 + lane * 8]     =
            make_float4(pv[0], pv[1], pv[2], pv[3]);
        *(float4*)&Ps[warp * 256 + lane * 8 + 4] =
            make_float4(pv[4], pv[5], pv[6], pv[7]);
        __syncwarp();

        // phase 3: o update; lane owns dims 4*lane..4*lane+3
        #pragma unroll
        for (int rr = 0; rr < 8; rr++) {
            o[rr].x *= corr[rr]; o[rr].y *= corr[rr];
            o[rr].z *= corr[rr]; o[rr].w *= corr[rr];
        }
        #pragma unroll 8
        for (int j = 0; j < FA_BN; j++) {
            float4 p0 = *(const float4*)&Ps[warp * 256 + j * 8];      // bcast
            float4 p1 = *(const float4*)&Ps[warp * 256 + j * 8 + 4];  // bcast
            float4 v4 = *(const float4*)&Vst[j * KPAD + 4 * lane];
            o[0].x += p0.x * v4.x; o[0].y += p0.x * v4.y;
            o[0].z += p0.x * v4.z; o[0].w += p0.x * v4.w;
            o[1].x += p0.y * v4.x; o[1].y += p0.y * v4.y;
            o[1].z += p0.y * v4.z; o[1].w += p0.y * v4.w;
            o[2].x += p0.z * v4.x; o[2].y += p0.z * v4.y;
            o[2].z += p0.z * v4.z; o[2].w += p0.z * v4.w;
            o[3].x += p0.w * v4.x; o[3].y += p0.w * v4.y;
            o[3].z += p0.w * v4.z; o[3].w += p0.w * v4.w;
            o[4].x += p1.x * v4.x; o[4].y += p1.x * v4.y;
            o[4].z += p1.x * v4.z; o[4].w += p1.x * v4.w;
            o[5].x += p1.y * v4.x; o[5].y += p1.y * v4.y;
            o[5].z += p1.y * v4.z; o[5].w += p1.y * v4.w;
            o[6].x += p1.z * v4.x; o[6].y += p1.z * v4.y;
            o[6].z += p1.z * v4.z; o[6].w += p1.z * v4.w;
            o[7].x += p1.w * v4.x; o[7].y += p1.w * v4.y;
            o[7].z += p1.w * v4.z; o[7].w += p1.w * v4.w;
        }
        CP_WAIT0();
        __syncthreads();
    }

    // epilogue: fp16 write straight into the wo-GEMM A operand
    #pragma unroll
    for (int rr = 0; rr < 8; rr++) {
        float inv = 1.0f / l[rr];
        uint2 H;
        H.x = pack_h2(o[rr].x * inv, o[rr].y * inv);
        H.y = pack_h2(o[rr].z * inv, o[rr].w * inv);
        *(uint2*)&g_ah[((size_t)(b * T_ + r0 + rr) * NH + h) * HD + 4 * lane] = H;
    }
}

// ---------------------------------------------------------------------------
// Launch
// ---------------------------------------------------------------------------
extern "C" void kernel_launch(void* const* d_in, const int* in_sizes, int n_in,
                              void* d_out, int out_size) {
    const float* x  = (const float*)d_in[0];
    const float* wq = (const float*)d_in[1];
    const float* wk = (const float*)d_in[2];
    const float* wv = (const float*)d_in[3];
    const float* wo = (const float*)d_in[4];
    float* out = (float*)d_out;

    float *q, *k, *v;
    cudaGetSymbolAddress((void**)&q, g_q);
    cudaGetSymbolAddress((void**)&k, g_k);
    cudaGetSymbolAddress((void**)&v, g_v);

    __half *xh, *ah, *wqh, *wql, *wkh, *wkl, *wvh, *wvl, *woh, *wol;
    cudaGetSymbolAddress((void**)&xh,  g_xh);
    cudaGetSymbolAddress((void**)&ah,  g_ah);
    cudaGetSymbolAddress((void**)&wqh, g_wqh); cudaGetSymbolAddress((void**)&wql, g_wql);
    cudaGetSymbolAddress((void**)&wkh, g_wkh); cudaGetSymbolAddress((void**)&wkl, g_wkl);
    cudaGetSymbolAddress((void**)&wvh, g_wvh); cudaGetSymbolAddress((void**)&wvl, g_wvl);
    cudaGetSymbolAddress((void**)&woh, g_woh); cudaGetSymbolAddress((void**)&wol, g_wol);

    cudaFuncSetAttribute(fgemm2_kernel,
                         cudaFuncAttributeMaxDynamicSharedMemorySize, GEMM_SMEM);
    cudaFuncSetAttribute(flash_attn_kernel,
                         cudaFuncAttributeMaxDynamicSharedMemorySize, FLASH_SMEM);

    // 1. RoPE cache
    rope_cache_kernel<<<T_, HD>>>();

    // 2. conversions: x -> fp16; weights -> transposed fp16 hi/lo split
    {
        int n4 = (M_ * D_) / 4;
        cvt_h_kernel<<<(n4 + 255) / 256, 256>>>(x, xh, n4);
        dim3 blk(32, 8);
        cvt_splitT_kernel<<<dim3(D_ / 32, D_ / 32), blk>>>(wq, wqh, wql, D_, D_);
        cvt_splitT_kernel<<<dim3(D_ / 32, D_ / 32), blk>>>(wo, woh, wol, D_, D_);
        cvt_splitT_kernel<<<dim3(KVD / 32, D_ / 32), blk>>>(wk, wkh, wkl, D_, KVD);
        cvt_splitT_kernel<<<dim3(KVD / 32, D_ / 32), blk>>>(wv, wvh, wvl, D_, KVD);
    }

    // 3. QKV projections (fp16 2-pass tensor-core GEMM)
    {
        dim3 gq(D_ / TBN, M_ / TBM);
        fgemm2_kernel<<<gq, 256, GEMM_SMEM>>>(xh, wqh, wql, q, D_, D_);
        dim3 gkv(KVD / TBN, M_ / TBM);
        fgemm2_kernel<<<gkv, 256, GEMM_SMEM>>>(xh, wkh, wkl, k, KVD, D_);
        fgemm2_kernel<<<gkv, 256, GEMM_SMEM>>>(xh, wvh, wvl, v, KVD, D_);
    }

    // 4. RoPE on q and k
    {
        int nq = M_ * NH * 64;
        rope_apply_kernel<<<(nq + 255) / 256, 256>>>(q, NH);
        int nk = M_ * NKV * 64;
        rope_apply_kernel<<<(nk + 255) / 256, 256>>>(k, NKV);
    }

    // 5. Causal GQA attention (writes fp16 g_ah directly)
    {
        dim3 g(T_ / FA_QROWS, B_ * NKV);
        flash_attn_kernel<<<g, 512, FLASH_SMEM>>>();
    }

    // 6. Output projection -> d_out
    {
        dim3 go(D_ / TBN, M_ / TBM);
        fgemm2_kernel<<<go, 256, GEMM_SMEM>>>(ah, woh, wol, out, D_, D_);
    }
}